// round 1
// baseline (speedup 1.0000x reference)
#include <cuda_runtime.h>
#include <cuda_bf16.h>

// Problem constants (fixed by setup_inputs)
#define B_    64
#define L_    16384
#define D_    64
#define KSEL  256
#define TILE  128        // keys per CTA in sim kernel
#define ROWW  68         // padded row width (words) for conflict-free SMEM
#define NBINS 4096       // top-12-bit histogram
#define CAP   4096       // candidate capacity

// Scratch: similarity matrix (B x L) = 4 MB
__device__ float g_sim[B_ * L_];

// ---------------------------------------------------------------------------
// Kernel A: sim[b,l] = g * dot(q_b, k_bl) * rsqrt(|q_b|^2) * rsqrt(|k_bl|^2)
// ---------------------------------------------------------------------------
__global__ void __launch_bounds__(TILE) sim_kernel(
    const float* __restrict__ q,
    const float* __restrict__ keys,
    const float* __restrict__ gp)
{
    __shared__ __align__(16) float4 qsm[D_ / 4];
    __shared__ __align__(16) float  tile[TILE * ROWW];

    const int b   = blockIdx.y;
    const int t0  = blockIdx.x * TILE;
    const int tid = threadIdx.x;

    if (tid < D_ / 4)
        qsm[tid] = reinterpret_cast<const float4*>(q + b * D_)[tid];

    // Stage key tile: linear float4 index f over [0, TILE*16); coalesced LDG.
    const float4* src = reinterpret_cast<const float4*>(
        keys + (size_t)b * L_ * D_ + (size_t)t0 * D_);
    float4 v[16];
#pragma unroll
    for (int j = 0; j < 16; j++)
        v[j] = src[j * TILE + tid];

    __syncthreads();  // qsm visible

    float qq = 0.f;
#pragma unroll
    for (int i = 0; i < D_ / 4; i++) {
        float4 t = qsm[i];
        qq += t.x * t.x + t.y * t.y + t.z * t.z + t.w * t.w;
    }
    const float gscale = gp[0];
    const float rq = gscale * rsqrtf(qq);

#pragma unroll
    for (int j = 0; j < 16; j++) {
        int f = j * TILE + tid;             // float4 index in tile
        int l = f >> 4;                      // key within tile
        int c = f & 15;                      // float4 chunk within key
        *reinterpret_cast<float4*>(&tile[l * ROWW + c * 4]) = v[j];
    }
    __syncthreads();

    float dot = 0.f, kk = 0.f;
#pragma unroll
    for (int i = 0; i < 16; i++) {
        float4 kv = *reinterpret_cast<const float4*>(&tile[tid * ROWW + i * 4]);
        float4 qv = qsm[i];
        dot += qv.x * kv.x + qv.y * kv.y + qv.z * kv.z + qv.w * kv.w;
        kk  += kv.x * kv.x + kv.y * kv.y + kv.z * kv.z + kv.w * kv.w;
    }
    g_sim[b * L_ + t0 + tid] = dot * rq * rsqrtf(kk);
}

// ---------------------------------------------------------------------------
// Kernel B: per-batch exact top-256 (desc value, asc index ties) + softmax +
// value gather. One CTA per batch, 512 threads.
// ---------------------------------------------------------------------------
__device__ __forceinline__ unsigned f2u(float f) {
    unsigned b = __float_as_uint(f);
    return (b & 0x80000000u) ? ~b : (b | 0x80000000u);
}
__device__ __forceinline__ float u2f(unsigned u) {
    unsigned b = (u & 0x80000000u) ? (u & 0x7FFFFFFFu) : ~u;
    return __uint_as_float(b);
}

// Warp-level: given per-lane counts (lane order = descending-value order is
// lane-index ASCENDING over bins? No — bins ascend with lane; we want suffix
// sums from the TOP, i.e. over lanes ABOVE me). Returns selected lane and its
// exclusive-above count (count in strictly higher lanes).
__device__ __forceinline__ int suffix_select(unsigned part, unsigned need,
                                             unsigned& above_out, int lane) {
    unsigned suf = part;  // inclusive suffix: sum part[lane..31]
#pragma unroll
    for (int o = 1; o < 32; o <<= 1) {
        unsigned t = __shfl_down_sync(0xFFFFFFFFu, suf, o);
        if (lane + o < 32) suf += t;
    }
    unsigned above = suf - part;  // strictly-higher-lane count
    unsigned m = __ballot_sync(0xFFFFFFFFu,
                               (above < need) && (above + part >= need));
    int sel = __ffs(m) - 1;      // unique
    above_out = __shfl_sync(0xFFFFFFFFu, above, sel);
    return sel;
}

__global__ void __launch_bounds__(512) topk_kernel(
    const float* __restrict__ values,
    float* __restrict__ out)
{
    extern __shared__ __align__(16) unsigned long long sm8[];
    unsigned long long* cand = sm8;                           // CAP * 8B
    unsigned* U    = (unsigned*)(cand + CAP);                 // L_ * 4B
    unsigned* hist = U + L_;                                  // NBINS * 4B

    __shared__ unsigned s_bin, s_above;
    __shared__ int s_ncand;
    __shared__ float s_e[KSEL];
    __shared__ float s_sum;

    const int b   = blockIdx.x;
    const int tid = threadIdx.x;
    const int T   = blockDim.x;

    // 1. load sims, map to order-preserving uints
    for (int i = tid; i < L_; i += T)
        U[i] = f2u(g_sim[b * L_ + i]);
    for (int i = tid; i < NBINS; i += T)
        hist[i] = 0;
    if (tid == 0) s_ncand = 0;
    __syncthreads();

    // 2. 12-bit histogram
    for (int i = tid; i < L_; i += T)
        atomicAdd(&hist[U[i] >> 20], 1u);
    __syncthreads();

    // 3. threshold-bin select (one warp)
    if (tid < 32) {
        const int lane = tid;
        // level 1: 32 groups of 128 bins
        unsigned part = 0;
        {
            int base = lane * 128;
            for (int j = 0; j < 128; j++) part += hist[base + j];
        }
        unsigned above1;
        int g1 = suffix_select(part, KSEL, above1, lane);
        // level 2: 32 sub-groups of 4 bins within group g1
        int base2 = g1 * 128 + lane * 4;
        unsigned part2 = hist[base2] + hist[base2 + 1] +
                         hist[base2 + 2] + hist[base2 + 3];
        unsigned above2;
        int g2 = suffix_select(part2, KSEL - above1, above2, lane);
        // level 3: 4 bins serial (all lanes compute identically)
        int bin_base = g1 * 128 + g2 * 4;
        unsigned acc = above1 + above2;
        int bin = bin_base;
        unsigned cnt_above = acc;
        for (int j = 3; j >= 0; j--) {
            unsigned h = hist[bin_base + j];
            if (acc + h >= KSEL) { bin = bin_base + j; cnt_above = acc; break; }
            acc += h;
        }
        if (lane == 0) { s_bin = (unsigned)bin; s_above = cnt_above; }
    }
    __syncthreads();

    // 4. collect candidates: everything >= bin floor (superset of top-K)
    const unsigned lo = s_bin << 20;
    for (int i = tid; i < L_; i += T) {
        unsigned u = U[i];
        if (u >= lo) {
            int p = atomicAdd(&s_ncand, 1);
            if (p < CAP)
                cand[p] = ((unsigned long long)u << 32) | (unsigned)(~i);
        }
    }
    __syncthreads();

    int n = s_ncand;
    if (n > CAP) n = CAP;
    int sz = KSEL;
    while (sz < n) sz <<= 1;
    for (int i = n + tid; i < sz; i += T) cand[i] = 0ull;  // sinks to bottom
    __syncthreads();

    // 5. bitonic sort, descending by (u, ~idx) => desc value, asc index ties
    for (int kk = 2; kk <= sz; kk <<= 1) {
        for (int j = kk >> 1; j > 0; j >>= 1) {
            for (int i = tid; i < sz; i += T) {
                int ixj = i ^ j;
                if (ixj > i) {
                    unsigned long long a = cand[i], c = cand[ixj];
                    bool desc = (i & kk) == 0;
                    if (desc ? (a < c) : (a > c)) {
                        cand[i] = c; cand[ixj] = a;
                    }
                }
            }
            __syncthreads();
        }
    }

    // 6. softmax over top-256 (cand[0] is the max), gather values, write out
    float maxs = u2f((unsigned)(cand[0] >> 32));
    if (tid < KSEL) {
        float s = u2f((unsigned)(cand[tid] >> 32));
        s_e[tid] = expf(s - maxs);
    }
    __syncthreads();
    if (tid < 32) {
        float acc = 0.f;
        for (int j = tid; j < KSEL; j += 32) acc += s_e[j];
#pragma unroll
        for (int o = 16; o > 0; o >>= 1)
            acc += __shfl_xor_sync(0xFFFFFFFFu, acc, o);
        if (tid == 0) s_sum = acc;
    }
    __syncthreads();
    if (tid < KSEL) {
        int idx = (int)(~(unsigned)cand[tid]);
        out[b * KSEL + tid]                = values[b * L_ + idx];   // values_sel
        out[B_ * KSEL + b * KSEL + tid]    = s_e[tid] / s_sum;       // weights
    }
}

// ---------------------------------------------------------------------------
extern "C" void kernel_launch(void* const* d_in, const int* in_sizes, int n_in,
                              void* d_out, int out_size)
{
    const float* q      = (const float*)d_in[0];
    const float* keys   = (const float*)d_in[1];
    const float* values = (const float*)d_in[2];
    const float* g      = (const float*)d_in[3];
    float* out = (float*)d_out;

    (void)in_sizes; (void)n_in; (void)out_size;

    // Kernel A: similarities
    dim3 gridA(L_ / TILE, B_);
    sim_kernel<<<gridA, TILE>>>(q, keys, g);

    // Kernel B: top-k + softmax + gather (dynamic smem > 48KB)
    const size_t smemB = (size_t)CAP * 8 + (size_t)L_ * 4 + (size_t)NBINS * 4;
    cudaFuncSetAttribute(topk_kernel,
                         cudaFuncAttributeMaxDynamicSharedMemorySize,
                         (int)smemB);
    topk_kernel<<<B_, 512, smemB>>>(values, out);
}

// round 2
// speedup vs baseline: 1.1647x; 1.1647x over previous
#include <cuda_runtime.h>
#include <cuda_bf16.h>

// Problem constants (fixed by setup_inputs)
#define B_    64
#define L_    16384
#define D_    64
#define KSEL  256
#define TILE  128        // keys per CTA in sim kernel
#define ROWW  68         // padded row width (words) for conflict-free SMEM
#define NBINS 4096       // top-12-bit histogram
#define CAP   4096       // candidate capacity

// Scratch: similarity matrix (B x L) = 4 MB
__device__ float g_sim[B_ * L_];
// Per-batch histogram, built by kernel A, consumed+rezeroed by kernel B.
// Zero-initialized at module load; B restores zeros each call -> deterministic.
__device__ unsigned g_hist[B_ * NBINS];

__device__ __forceinline__ unsigned f2u(float f) {
    unsigned b = __float_as_uint(f);
    return (b & 0x80000000u) ? ~b : (b | 0x80000000u);
}
__device__ __forceinline__ float u2f(unsigned u) {
    unsigned b = (u & 0x80000000u) ? (u & 0x7FFFFFFFu) : ~u;
    return __uint_as_float(b);
}

// ---------------------------------------------------------------------------
// Kernel A: sim[b,l] = g * dot(q_b,k_bl) * rsqrt(|q_b|^2) * rsqrt(|k_bl|^2)
// cp.async staging (no register round trip), fused histogram build.
// ---------------------------------------------------------------------------
__global__ void __launch_bounds__(TILE) sim_kernel(
    const float* __restrict__ q,
    const float* __restrict__ keys,
    const float* __restrict__ gp)
{
    __shared__ __align__(16) float4 qsm[D_ / 4];
    __shared__ __align__(16) float  tile[TILE * ROWW];

    const int b   = blockIdx.y;
    const int t0  = blockIdx.x * TILE;
    const int tid = threadIdx.x;

    if (tid < D_ / 4)
        qsm[tid] = reinterpret_cast<const float4*>(q + b * D_)[tid];

    // Stage key tile via cp.async: coalesced global reads, padded smem layout.
    const float4* src = reinterpret_cast<const float4*>(
        keys + (size_t)b * L_ * D_ + (size_t)t0 * D_);
#pragma unroll
    for (int j = 0; j < 16; j++) {
        int f = j * TILE + tid;              // float4 index in tile
        int l = f >> 4;                       // key within tile
        int c = f & 15;                       // float4 chunk within key
        unsigned dst = (unsigned)__cvta_generic_to_shared(&tile[l * ROWW + c * 4]);
        asm volatile("cp.async.cg.shared.global [%0], [%1], 16;\n"
                     :: "r"(dst), "l"(src + f));
    }
    asm volatile("cp.async.commit_group;\n");

    __syncthreads();  // qsm visible

    float qq = 0.f;
#pragma unroll
    for (int i = 0; i < D_ / 4; i++) {
        float4 t = qsm[i];
        qq += t.x * t.x + t.y * t.y + t.z * t.z + t.w * t.w;
    }
    const float rq = gp[0] * rsqrtf(qq);

    asm volatile("cp.async.wait_group 0;\n");
    __syncthreads();  // tile visible to all

    float dot = 0.f, kk = 0.f;
#pragma unroll
    for (int i = 0; i < 16; i++) {
        float4 kv = *reinterpret_cast<const float4*>(&tile[tid * ROWW + i * 4]);
        float4 qv = qsm[i];
        dot += qv.x * kv.x + qv.y * kv.y + qv.z * kv.z + qv.w * kv.w;
        kk  += kv.x * kv.x + kv.y * kv.y + kv.z * kv.z + kv.w * kv.w;
    }
    float sim = dot * rq * rsqrtf(kk);
    g_sim[b * L_ + t0 + tid] = sim;
    atomicAdd(&g_hist[b * NBINS + (f2u(sim) >> 20)], 1u);   // RED.global
}

// ---------------------------------------------------------------------------
// Warp-level suffix select (lanes = ascending bins; count from the top).
// ---------------------------------------------------------------------------
__device__ __forceinline__ int suffix_select(unsigned part, unsigned need,
                                             unsigned& above_out, int lane) {
    unsigned suf = part;
#pragma unroll
    for (int o = 1; o < 32; o <<= 1) {
        unsigned t = __shfl_down_sync(0xFFFFFFFFu, suf, o);
        if (lane + o < 32) suf += t;
    }
    unsigned above = suf - part;
    unsigned m = __ballot_sync(0xFFFFFFFFu,
                               (above < need) && (above + part >= need));
    int sel = __ffs(m) - 1;
    above_out = __shfl_sync(0xFFFFFFFFu, above, sel);
    return sel;
}

// ---------------------------------------------------------------------------
// Kernel B: per-batch exact top-256 + softmax + gather. One CTA per batch.
// Single pass over L (histogram came from kernel A).
// ---------------------------------------------------------------------------
__global__ void __launch_bounds__(1024) topk_kernel(
    const float* __restrict__ values,
    float* __restrict__ out)
{
    extern __shared__ __align__(16) unsigned long long sm8[];
    unsigned long long* cand = sm8;                 // CAP * 8B = 32 KB
    unsigned* hist = (unsigned*)(cand + CAP);       // NBINS * 4B = 16 KB

    __shared__ unsigned s_bin;
    __shared__ int s_ncand;
    __shared__ float s_e[KSEL];
    __shared__ float s_sum;

    const int b   = blockIdx.x;
    const int tid = threadIdx.x;
    const int T   = blockDim.x;

    // 1. pull histogram into smem; restore zeros for next graph replay
    for (int i = tid; i < NBINS; i += T) {
        hist[i] = g_hist[b * NBINS + i];
        g_hist[b * NBINS + i] = 0;
    }
    if (tid == 0) s_ncand = 0;
    __syncthreads();

    // 2. threshold-bin select (one warp, 3 levels: 128 / 4 / 1 bins)
    if (tid < 32) {
        const int lane = tid;
        unsigned part = 0;
        {
            int base = lane * 128;
            for (int j = 0; j < 128; j++) part += hist[base + j];
        }
        unsigned above1;
        int g1 = suffix_select(part, KSEL, above1, lane);
        int base2 = g1 * 128 + lane * 4;
        unsigned part2 = hist[base2] + hist[base2 + 1] +
                         hist[base2 + 2] + hist[base2 + 3];
        unsigned above2;
        int g2 = suffix_select(part2, KSEL - above1, above2, lane);
        int bin_base = g1 * 128 + g2 * 4;
        unsigned acc = above1 + above2;
        int bin = bin_base;
        for (int j = 3; j >= 0; j--) {
            unsigned h = hist[bin_base + j];
            if (acc + h >= KSEL) { bin = bin_base + j; break; }
            acc += h;
        }
        if (lane == 0) s_bin = (unsigned)bin;
    }
    __syncthreads();

    // 3. collect candidates >= bin floor (superset of top-K)
    const unsigned lo = s_bin << 20;
    for (int i = tid; i < L_; i += T) {
        unsigned u = f2u(g_sim[b * L_ + i]);
        if (u >= lo) {
            int p = atomicAdd(&s_ncand, 1);
            if (p < CAP)
                cand[p] = ((unsigned long long)u << 32) | (unsigned)(~i);
        }
    }
    __syncthreads();

    int n = s_ncand;
    if (n > CAP) n = CAP;
    int sz = KSEL;
    while (sz < n) sz <<= 1;
    for (int i = n + tid; i < sz; i += T) cand[i] = 0ull;  // sinks to bottom
    __syncthreads();

    // 4. bitonic sort, descending by (u, ~idx) => desc value, asc index ties
    for (int kk = 2; kk <= sz; kk <<= 1) {
        for (int j = kk >> 1; j > 0; j >>= 1) {
            for (int i = tid; i < sz; i += T) {
                int ixj = i ^ j;
                if (ixj > i) {
                    unsigned long long a = cand[i], c = cand[ixj];
                    bool desc = (i & kk) == 0;
                    if (desc ? (a < c) : (a > c)) {
                        cand[i] = c; cand[ixj] = a;
                    }
                }
            }
            __syncthreads();
        }
    }

    // 5. softmax over top-256 (cand[0] is max), gather values, write out
    float maxs = u2f((unsigned)(cand[0] >> 32));
    if (tid < KSEL) {
        float s = u2f((unsigned)(cand[tid] >> 32));
        s_e[tid] = expf(s - maxs);
    }
    __syncthreads();
    if (tid < 32) {
        float acc = 0.f;
        for (int j = tid; j < KSEL; j += 32) acc += s_e[j];
#pragma unroll
        for (int o = 16; o > 0; o >>= 1)
            acc += __shfl_xor_sync(0xFFFFFFFFu, acc, o);
        if (tid == 0) s_sum = acc;
    }
    __syncthreads();
    if (tid < KSEL) {
        int idx = (int)(~(unsigned)cand[tid]);
        out[b * KSEL + tid]             = values[b * L_ + idx];   // values_sel
        out[B_ * KSEL + b * KSEL + tid] = s_e[tid] / s_sum;       // weights
    }
}

// ---------------------------------------------------------------------------
extern "C" void kernel_launch(void* const* d_in, const int* in_sizes, int n_in,
                              void* d_out, int out_size)
{
    const float* q      = (const float*)d_in[0];
    const float* keys   = (const float*)d_in[1];
    const float* values = (const float*)d_in[2];
    const float* g      = (const float*)d_in[3];
    float* out = (float*)d_out;

    (void)in_sizes; (void)n_in; (void)out_size;

    dim3 gridA(L_ / TILE, B_);
    sim_kernel<<<gridA, TILE>>>(q, keys, g);

    const size_t smemB = (size_t)CAP * 8 + (size_t)NBINS * 4;  // 48 KB
    cudaFuncSetAttribute(topk_kernel,
                         cudaFuncAttributeMaxDynamicSharedMemorySize,
                         (int)smemB);
    topk_kernel<<<B_, 1024, smemB>>>(values, out);
}